// round 2
// baseline (speedup 1.0000x reference)
#include <cuda_runtime.h>
#include <cuda_bf16.h>
#include <math.h>
#include <stdint.h>

#define BATCH 64
#define SEQ   512
#define DIN   1024
#define DENSE 1024
#define HID   768
#define G4    (4*HID)    // 3072
#define E2    (2*HID)    // 1536
#define NINT  60
#define MT    (BATCH*SEQ) // 32768

// ---------------- static device buffers (no runtime allocation) ----------------
__device__ float d_reg [(size_t)MT * DENSE];
__device__ float d_xpf [(size_t)MT * G4];
__device__ float d_xpb [(size_t)MT * G4];
__device__ float d_enc0[(size_t)MT * E2];
__device__ float d_enc1[(size_t)MT * E2];
__device__ float d_whT [4][(size_t)G4 * HID];   // [layer*2+dir][n][k]
__device__ float d_h   [2][2][BATCH][HID];      // [parity][dir][b][k]
__device__ float d_scores[MT];
__device__ float d_attn  [MT];
__device__ float d_ctx [BATCH * E2];
__device__ float d_ctx2[BATCH * E2];
__device__ unsigned d_bar_cnt = 0;
__device__ volatile unsigned d_bar_gen = 0;

__device__ __forceinline__ float* buf_sel(int s) {
    switch (s) {
        case 0: return d_reg;
        case 1: return d_xpf;
        case 2: return d_xpb;
        case 3: return d_enc0;
        default: return d_enc1;
    }
}

// ---------------- software grid barrier (all blocks co-resident) ----------------
__device__ __forceinline__ void grid_bar() {
    __syncthreads();
    if (threadIdx.x == 0) {
        unsigned gen = d_bar_gen;          // read phase BEFORE arriving
        __threadfence();
        unsigned arrived = atomicAdd(&d_bar_cnt, 1u);
        if (arrived == gridDim.x - 1) {
            d_bar_cnt = 0;
            __threadfence();
            d_bar_gen = gen + 1;
        } else {
            while (d_bar_gen == gen) { }
        }
        __threadfence();
    }
    __syncthreads();
}

// ================= bf16x3 tensor-core GEMM =================
// C[M,N] = act(A[M,K] @ W[K,N] + bias), fp32 in/out, fp32-class accuracy via
// 2-way bf16 split: A = Ah + Al, B = Bh + Bl; C ~= Ah*Bh + Ah*Bl + Al*Bh.
// Tile 128x128, kt=32, 256 threads (8 warps, 2x4), warp tile 64x32,
// mma.sync.m16n8k16 bf16 (HMMA fallback path on sm_103a).

#define LDSM4(R, addr) \
    asm volatile("ldmatrix.sync.aligned.m8n8.x4.shared.b16 {%0,%1,%2,%3}, [%4];" \
        : "=r"((R)[0]), "=r"((R)[1]), "=r"((R)[2]), "=r"((R)[3]) : "r"(addr))
#define LDSM4T(R, addr) \
    asm volatile("ldmatrix.sync.aligned.m8n8.x4.trans.shared.b16 {%0,%1,%2,%3}, [%4];" \
        : "=r"((R)[0]), "=r"((R)[1]), "=r"((R)[2]), "=r"((R)[3]) : "r"(addr))
#define MMA16816(d, a, bb0, bb1) \
    asm volatile("mma.sync.aligned.m16n8k16.row.col.f32.bf16.bf16.f32 " \
        "{%0,%1,%2,%3},{%4,%5,%6,%7},{%8,%9},{%0,%1,%2,%3};" \
        : "+f"((d)[0]), "+f"((d)[1]), "+f"((d)[2]), "+f"((d)[3]) \
        : "r"((a)[0]), "r"((a)[1]), "r"((a)[2]), "r"((a)[3]), "r"(bb0), "r"(bb1))

__device__ __forceinline__ uint32_t sptr(const void* p) {
    return (uint32_t)__cvta_generic_to_shared(p);
}

__device__ __forceinline__ void split2(float x, float y, uint32_t& hi, uint32_t& lo) {
    __nv_bfloat162 h = __floats2bfloat162_rn(x, y);
    float rx = x - __bfloat162float(h.x);
    float ry = y - __bfloat162float(h.y);
    __nv_bfloat162 l = __floats2bfloat162_rn(rx, ry);
    hi = *(uint32_t*)&h;
    lo = *(uint32_t*)&l;
}

#define A_STRIDE 40   // bf16 elems per smem row (32 + 8 pad)
#define B_STRIDE 136  // bf16 elems per smem row (128 + 8 pad)

template <bool TANH>
__global__ void __launch_bounds__(256) gemm_bf16x3(
    const float* __restrict__ Aext, int aSel,
    const float* __restrict__ W, const float* __restrict__ bias,
    int cSel, int M, int N, int K)
{
    const float* A = (aSel < 0) ? Aext : buf_sel(aSel);
    float* C = buf_sel(cSel);

    __shared__ __nv_bfloat16 Ah_s[128 * A_STRIDE];
    __shared__ __nv_bfloat16 Al_s[128 * A_STRIDE];
    __shared__ __nv_bfloat16 Bh_s[32 * B_STRIDE];
    __shared__ __nv_bfloat16 Bl_s[32 * B_STRIDE];

    const int tid  = threadIdx.x;
    const int lane = tid & 31;
    const int warp = tid >> 5;
    const int wm   = warp & 1;   // 0/1 -> 64-row half
    const int wn   = warp >> 1;  // 0..3 -> 32-col quarter
    const int bm   = blockIdx.y * 128;
    const int bn   = blockIdx.x * 128;

    // ldmatrix per-lane address components
    const int arow = wm * 64 + (lane & 15);
    const int akof = (lane >> 4) * 8;
    const int bkof = (lane & 7) + ((lane >> 3) & 1) * 8;
    const int bnof = wn * 32 + (lane >> 4) * 8;

    const uint32_t ah_base = sptr(Ah_s) + (uint32_t)(arow * A_STRIDE + akof) * 2;
    const uint32_t al_base = sptr(Al_s) + (uint32_t)(arow * A_STRIDE + akof) * 2;
    const uint32_t bh_base = sptr(Bh_s) + (uint32_t)(bkof * B_STRIDE + bnof) * 2;
    const uint32_t bl_base = sptr(Bl_s) + (uint32_t)(bkof * B_STRIDE + bnof) * 2;

    float acc[4][4][4];
#pragma unroll
    for (int i = 0; i < 4; i++)
#pragma unroll
        for (int j = 0; j < 4; j++)
#pragma unroll
            for (int r = 0; r < 4; r++) acc[i][j][r] = 0.f;

    for (int k0 = 0; k0 < K; k0 += 32) {
        __syncthreads();  // previous compute done reading smem
        // ---- stage A tile: 128 x 32 fp32 -> bf16 hi/lo ----
#pragma unroll
        for (int i = 0; i < 4; i++) {
            int idx = tid + i * 256;          // 0..1023 float4s
            int row = idx >> 3;
            int kq  = (idx & 7) * 4;
            float4 v = *(const float4*)&A[(size_t)(bm + row) * K + k0 + kq];
            uint2 hi2, lo2;
            split2(v.x, v.y, hi2.x, lo2.x);
            split2(v.z, v.w, hi2.y, lo2.y);
            *(uint2*)&Ah_s[row * A_STRIDE + kq] = hi2;
            *(uint2*)&Al_s[row * A_STRIDE + kq] = lo2;
        }
        // ---- stage B tile: 32 x 128 fp32 -> bf16 hi/lo ----
#pragma unroll
        for (int i = 0; i < 4; i++) {
            int idx = tid + i * 256;
            int kr = idx >> 5;
            int nq = (idx & 31) * 4;
            float4 v = *(const float4*)&W[(size_t)(k0 + kr) * N + bn + nq];
            uint2 hi2, lo2;
            split2(v.x, v.y, hi2.x, lo2.x);
            split2(v.z, v.w, hi2.y, lo2.y);
            *(uint2*)&Bh_s[kr * B_STRIDE + nq] = hi2;
            *(uint2*)&Bl_s[kr * B_STRIDE + nq] = lo2;
        }
        __syncthreads();

#pragma unroll
        for (int ks = 0; ks < 2; ks++) {
            uint32_t Ahf[4][4], Alf[4][4], Bhf[2][4], Blf[2][4];
#pragma unroll
            for (int mt = 0; mt < 4; mt++) {
                uint32_t off = (uint32_t)(mt * 16 * A_STRIDE + ks * 16) * 2;
                LDSM4(Ahf[mt], ah_base + off);
                LDSM4(Alf[mt], al_base + off);
            }
#pragma unroll
            for (int np = 0; np < 2; np++) {
                uint32_t off = (uint32_t)(ks * 16 * B_STRIDE + np * 16) * 2;
                LDSM4T(Bhf[np], bh_base + off);
                LDSM4T(Blf[np], bl_base + off);
            }
#pragma unroll
            for (int mt = 0; mt < 4; mt++) {
#pragma unroll
                for (int nt = 0; nt < 4; nt++) {
                    int np = nt >> 1, q = (nt & 1) * 2;
                    MMA16816(acc[mt][nt], Ahf[mt], Bhf[np][q], Bhf[np][q + 1]);
                    MMA16816(acc[mt][nt], Ahf[mt], Blf[np][q], Blf[np][q + 1]);
                    MMA16816(acc[mt][nt], Alf[mt], Bhf[np][q], Bhf[np][q + 1]);
                }
            }
        }
    }

    // ---- epilogue ----
    const int gr = lane >> 2;          // group row 0..7
    const int gc = (lane & 3) * 2;     // col pair
#pragma unroll
    for (int mt = 0; mt < 4; mt++) {
        int row = bm + wm * 64 + mt * 16 + gr;
#pragma unroll
        for (int nt = 0; nt < 4; nt++) {
            int col = bn + wn * 32 + nt * 8 + gc;
            float b0 = bias ? bias[col] : 0.f;
            float b1 = bias ? bias[col + 1] : 0.f;
            float2 v0, v1;
            v0.x = acc[mt][nt][0] + b0;
            v0.y = acc[mt][nt][1] + b1;
            v1.x = acc[mt][nt][2] + b0;
            v1.y = acc[mt][nt][3] + b1;
            if (TANH) {
                v0.x = tanhf(v0.x); v0.y = tanhf(v0.y);
                v1.x = tanhf(v1.x); v1.y = tanhf(v1.y);
            }
            *(float2*)&C[(size_t)row * N + col]       = v0;
            *(float2*)&C[(size_t)(row + 8) * N + col] = v1;
        }
    }
}

// ---------------- Wh transpose: Wt[n][k] = W[k][n], K=768, N=3072 ----------------
__global__ void transpose_wh(const float* __restrict__ W, int widx) {
    __shared__ float tile[32][33];
    float* Wt = d_whT[widx];
    int k0 = blockIdx.y * 32, n0 = blockIdx.x * 32;
    int tx = threadIdx.x, ty = threadIdx.y;
    for (int i = ty; i < 32; i += 8)
        tile[i][tx] = W[(size_t)(k0 + i) * G4 + n0 + tx];
    __syncthreads();
    for (int i = ty; i < 32; i += 8)
        Wt[(size_t)(n0 + i) * HID + k0 + tx] = tile[tx][i];
}

// ---------------- persistent BiLSTM layer (fwd+bwd), 128 blocks x 384 threads ----------------
// Block = (dir, 16-batch tile, 48-j tile). Thread = 2 batches x (j) x 4 gates.
// Cell state c lives in registers for all 512 steps; h ping-pongs in global.
__global__ void __launch_bounds__(384, 1) lstm_layer(int layer, const int* __restrict__ lens) {
    __shared__ float Hs[16][HID];  // 48KB: h snapshot for this block's 16 batches

    const int tid = threadIdx.x;
    const int dir = blockIdx.x >> 6;      // 0 fwd, 1 bwd
    const int rem = blockIdx.x & 63;
    const int b0 = (rem >> 4) * 16;       // batch tile base
    const int jbase = (rem & 15) * 48;    // j tile base
    const int tx = tid % 48;
    const int ty = tid / 48;              // 0..7
    const int j = jbase + tx;
    const int bloc0 = ty * 2;

    const float* xp = dir ? d_xpb : d_xpf;
    const float* whT = d_whT[layer * 2 + dir];
    float* enc = layer ? d_enc1 : d_enc0;

    int myb[2], myL[2];
#pragma unroll
    for (int bi = 0; bi < 2; bi++) {
        myb[bi] = b0 + bloc0 + bi;
        myL[bi] = lens[myb[bi]];
    }
    int maxL = max(myL[0], myL[1]);

    // init h parity-0 (this block's slice) and register cell state
    for (int i = tid; i < 16 * 48; i += 384) {
        d_h[0][dir][b0 + (i / 48)][jbase + (i % 48)] = 0.f;
    }
    float c2[2] = {0.f, 0.f};
    grid_bar();

    const float* wr0 = whT + (size_t)(0 * HID + j) * HID;
    const float* wr1 = whT + (size_t)(1 * HID + j) * HID;
    const float* wr2 = whT + (size_t)(2 * HID + j) * HID;
    const float* wr3 = whT + (size_t)(3 * HID + j) * HID;

    for (int t = 0; t < SEQ; t++) {
        const int p = t & 1;
        // stage h snapshot (L2-coherent loads; other blocks wrote it last step)
        const float4* hsrc = (const float4*)&d_h[p][dir][b0][0];
        float4* hdst = (float4*)&Hs[0][0];
#pragma unroll
        for (int i = 0; i < 8; i++)
            hdst[tid + i * 384] = __ldcg(hsrc + tid + i * 384);
        __syncthreads();

        float acc[2][4];
#pragma unroll
        for (int bi = 0; bi < 2; bi++)
#pragma unroll
            for (int g = 0; g < 4; g++) acc[bi][g] = 0.f;

        if (t < maxL) {
#pragma unroll 2
            for (int k = 0; k < HID; k += 4) {
                float4 w0 = *(const float4*)(wr0 + k);
                float4 w1 = *(const float4*)(wr1 + k);
                float4 w2 = *(const float4*)(wr2 + k);
                float4 w3 = *(const float4*)(wr3 + k);
#pragma unroll
                for (int bi = 0; bi < 2; bi++) {
                    float4 hv = *(const float4*)&Hs[bloc0 + bi][k];
                    acc[bi][0] += hv.x * w0.x + hv.y * w0.y + hv.z * w0.z + hv.w * w0.w;
                    acc[bi][1] += hv.x * w1.x + hv.y * w1.y + hv.z * w1.z + hv.w * w1.w;
                    acc[bi][2] += hv.x * w2.x + hv.y * w2.y + hv.z * w2.z + hv.w * w2.w;
                    acc[bi][3] += hv.x * w3.x + hv.y * w3.y + hv.z * w3.z + hv.w * w3.w;
                }
            }
        }

#pragma unroll
        for (int bi = 0; bi < 2; bi++) {
            const int b = myb[bi];
            const int L = myL[bi];
            const bool alive = (t < L);
            const int src = dir ? (alive ? (L - 1 - t) : t) : t;  // fwd: always t
            float hold = Hs[bloc0 + bi][j];
            float hnew, outv;
            if (alive) {
                const float* xr = xp + ((size_t)b * SEQ + src) * G4;
                float zi = acc[bi][0] + xr[j];
                float zf = acc[bi][1] + xr[HID + j];
                float zg = acc[bi][2] + xr[2 * HID + j];
                float zo = acc[bi][3] + xr[3 * HID + j];
                float si = 1.f / (1.f + expf(-zi));
                float sf = 1.f / (1.f + expf(-zf));
                float so = 1.f / (1.f + expf(-zo));
                float nc = sf * c2[bi] + si * tanhf(zg);
                c2[bi] = nc;
                hnew = so * tanhf(nc);
                outv = hnew;
            } else {
                hnew = hold;   // carry h across ping-pong
                outv = 0.f;    // masked positions: write 0 (never used downstream)
            }
            d_h[p ^ 1][dir][b][j] = hnew;
            enc[((size_t)b * SEQ + src) * E2 + dir * HID + j] = outv;
        }
        grid_bar();
    }
}

// ---------------- attention tail ----------------
__global__ void scores_kernel(const float* __restrict__ we) {  // ekey lives in d_xpf
    const int warp = threadIdx.x >> 5, lane = threadIdx.x & 31;
    const size_t row = (size_t)blockIdx.x * 8 + warp;
    const float* r = d_xpf + row * E2;
    float s = 0.f;
    for (int k = lane; k < E2; k += 32) s += r[k] * we[k];
#pragma unroll
    for (int o = 16; o; o >>= 1) s += __shfl_down_sync(0xffffffffu, s, o);
    if (!lane) d_scores[row] = s;
}

__global__ void softmax_kernel(const int* __restrict__ lens) {
    __shared__ float red[512];
    const int b = blockIdx.x, t = threadIdx.x;
    const int L = lens[b];
    float v = (t < L) ? d_scores[b * SEQ + t] : -INFINITY;
    red[t] = v;
    __syncthreads();
    for (int s = 256; s > 0; s >>= 1) { if (t < s) red[t] = fmaxf(red[t], red[t + s]); __syncthreads(); }
    float m = red[0];
    __syncthreads();
    float e = (t < L) ? expf(v - m) : 0.f;
    red[t] = e;
    __syncthreads();
    for (int s = 256; s > 0; s >>= 1) { if (t < s) red[t] += red[t + s]; __syncthreads(); }
    d_attn[b * SEQ + t] = e / red[0];
}

__global__ void context_kernel() {
    const int b = blockIdx.y;
    const int h = blockIdx.x * 256 + threadIdx.x;
    float acc = 0.f;
    const float* a = d_attn + b * SEQ;
    const float* e = d_enc1 + (size_t)b * SEQ * E2 + h;
    for (int t = 0; t < SEQ; t++) acc += a[t] * e[(size_t)t * E2];
    d_ctx[b * E2 + h] = acc;
}

__global__ void post_kernel(const float* __restrict__ Wp, const float* __restrict__ bp) {
    const int b = blockIdx.y;
    const int n = blockIdx.x * 256 + threadIdx.x;
    float acc = bp[n];
    const float* c = d_ctx + b * E2;
    for (int k = 0; k < E2; k++) acc += c[k] * Wp[(size_t)k * E2 + n];
    d_ctx2[b * E2 + n] = acc;
}

__global__ void intents_kernel(const float* __restrict__ Wi, const float* __restrict__ bi, float* __restrict__ out) {
    const int b = blockIdx.x, n = threadIdx.x;
    if (n >= NINT) return;
    float acc = bi[n];
    const float* c = d_ctx2 + b * E2;
    for (int k = 0; k < E2; k++) acc += c[k] * Wi[k * NINT + n];
    out[b * NINT + n] = acc;
}

// ---------------- launch ----------------
extern "C" void kernel_launch(void* const* d_in, const int* in_sizes, int n_in,
                              void* d_out, int out_size) {
    const float* X    = (const float*)d_in[0];
    const int*   lens = (const int*)  d_in[1];
    const int s = (n_in >= 23) ? 3 : 2;  // skip is_test if present
    const float* W_reg  = (const float*)d_in[s + 0];
    const float* b_reg  = (const float*)d_in[s + 1];
    const float* Wi0f   = (const float*)d_in[s + 2];
    const float* Wh0f   = (const float*)d_in[s + 3];
    const float* b0f    = (const float*)d_in[s + 4];
    const float* Wi0b   = (const float*)d_in[s + 5];
    const float* Wh0b   = (const float*)d_in[s + 6];
    const float* b0b    = (const float*)d_in[s + 7];
    const float* Wi1f   = (const float*)d_in[s + 8];
    const float* Wh1f   = (const float*)d_in[s + 9];
    const float* b1f    = (const float*)d_in[s + 10];
    const float* Wi1b   = (const float*)d_in[s + 11];
    const float* Wh1b   = (const float*)d_in[s + 12];
    const float* b1b    = (const float*)d_in[s + 13];
    const float* W_keys = (const float*)d_in[s + 14];
    const float* W_en   = (const float*)d_in[s + 15];
    const float* W_post = (const float*)d_in[s + 16];
    const float* b_post = (const float*)d_in[s + 17];
    const float* W_int  = (const float*)d_in[s + 18];
    const float* b_int  = (const float*)d_in[s + 19];

    // 1) pre-transpose recurrent weights
    {
        dim3 g(G4 / 32, HID / 32), b(32, 8);
        transpose_wh<<<g, b>>>(Wh0f, 0);
        transpose_wh<<<g, b>>>(Wh0b, 1);
        transpose_wh<<<g, b>>>(Wh1f, 2);
        transpose_wh<<<g, b>>>(Wh1b, 3);
    }

    // 2) reg = X @ W_reg + b_reg
    gemm_bf16x3<false><<<dim3(DENSE / 128, MT / 128), 256>>>(X, -1, W_reg, b_reg, 0, MT, DENSE, DIN);

    // 3) layer-0 input projections (bias folded)
    gemm_bf16x3<false><<<dim3(G4 / 128, MT / 128), 256>>>(nullptr, 0, Wi0f, b0f, 1, MT, G4, DENSE);
    gemm_bf16x3<false><<<dim3(G4 / 128, MT / 128), 256>>>(nullptr, 0, Wi0b, b0b, 2, MT, G4, DENSE);

    // 4) layer-0 recurrence -> enc0
    lstm_layer<<<128, 384>>>(0, lens);

    // 5) layer-1 input projections
    gemm_bf16x3<false><<<dim3(G4 / 128, MT / 128), 256>>>(nullptr, 3, Wi1f, b1f, 1, MT, G4, E2);
    gemm_bf16x3<false><<<dim3(G4 / 128, MT / 128), 256>>>(nullptr, 3, Wi1b, b1b, 2, MT, G4, E2);

    // 6) layer-1 recurrence -> enc1
    lstm_layer<<<128, 384>>>(1, lens);

    // 7) ekey = tanh(enc1 @ W_keys)  (stored in d_xpf)
    gemm_bf16x3<true><<<dim3(E2 / 128, MT / 128), 256>>>(nullptr, 4, W_keys, nullptr, 1, MT, E2, E2);

    // 8) attention tail
    scores_kernel<<<MT / 8, 256>>>(W_en);
    softmax_kernel<<<BATCH, 512>>>(lens);
    context_kernel<<<dim3(E2 / 256, BATCH), 256>>>();
    post_kernel<<<dim3(E2 / 256, BATCH), 256>>>(W_post, b_post);
    intents_kernel<<<BATCH, 64>>>(W_int, b_int, (float*)d_out);
}